// round 11
// baseline (speedup 1.0000x reference)
#include <cuda_runtime.h>

#define B_   256
#define M_   8
#define L_   64
#define E_   128
#define H_   8
#define HD_  16
#define QKV_ 384
#define QP_  392          // padded qkv row stride in smem
#define R_   (B_ * M_)    // 2048 rows

// Scratch (no allocation allowed -> __device__ globals)
__device__ float g_agg1[R_ * E_];        // after per-metapath linear, row = b*8+m
__device__ float g_qkv[R_ * QKV_];       // qkv rows
__device__ float g_WqkvT[E_ * QKV_];     // Wqkv transposed: [e][j]
__device__ float g_WoT[E_ * E_];         // Wo transposed:   [e][j]

// ---------------------------------------------------------------------------
// Kernel AB: fused gather + per-metapath linear.
// block = (m, 4-batch tile); grid (8, 64) = 512 blocks; 256 threads.
// Phase 1: gather 4 rows (thread = e x walk-half) into smem.
// Phase 2: mplinear GEMM from smem (col x rowgroup of 2, 8-deep prefetch).
// Also folds the weight transposes (128 elements per block).
// ---------------------------------------------------------------------------
__global__ void __launch_bounds__(256) k_gathermp(const int*   __restrict__ walks,
                                                  const float* __restrict__ node_table,
                                                  const float* __restrict__ fc1_b,
                                                  const float* __restrict__ edge_table,
                                                  const int*   __restrict__ mp_type_idx,
                                                  const float* __restrict__ W_mp,
                                                  const float* __restrict__ b_mp,
                                                  const float* __restrict__ Wqkv,
                                                  const float* __restrict__ Wo) {
    __shared__ int   s_idx[4][L_ * 3];              // 3 KB
    __shared__ float s_half[2][4][E_];              // 4 KB
    __shared__ __align__(16) float s_xT[E_][4];     // 2 KB, transposed agg tile

    const int m   = blockIdx.x;
    const int b0  = blockIdx.y * 4;
    const int tid = threadIdx.x;
    const int bid = blockIdx.y * 8 + blockIdx.x;    // 0..511

    // folded transpose: 128 elements per block (65536 total = 512*128)
    if (tid < 128) {
        int idx = bid * 128 + tid;
        if (idx < E_ * QKV_) {
            int j = idx / E_;
            int e = idx % E_;
            g_WqkvT[e * QKV_ + j] = Wqkv[idx];
        } else {
            int k2 = idx - E_ * QKV_;
            int j = k2 / E_;
            int e = k2 % E_;
            g_WoT[e * E_ + j] = Wo[k2];
        }
    }

    // stage walk indices for 4 rows
    for (int i = tid; i < 4 * L_ * 3; i += 256) {
        int r = i / (L_ * 3);
        int k = i % (L_ * 3);
        s_idx[r][k] = walks[(((b0 + r) * M_) + m) * (L_ * 3) + k];
    }
    __syncthreads();

    // ---- phase 1: gather.  thread = (e, walk-half h) ----
    {
        const int e  = tid & 127;
        const int h  = tid >> 7;
        const int l0 = h * 32;
        const float fb = fc1_b[e];
#pragma unroll
        for (int r = 0; r < 4; r++) {
            float a = 0.f;
#pragma unroll 8
            for (int l = l0; l < l0 + 32; l++) {
                int n1 = s_idx[r][3 * l + 0];
                int n2 = s_idx[r][3 * l + 1];
                int et = s_idx[r][3 * l + 2];
                float x1 = node_table[n1 * E_ + e] + fb;
                float x2 = node_table[n2 * E_ + e] + fb;
                float x3 = edge_table[et * E_ + e];
                a += x1 * x2 * x3;
            }
            s_half[h][r][e] = a;
        }
    }
    __syncthreads();

    // combine halves into transposed tile (mean over L)
    for (int i = tid; i < 4 * E_; i += 256) {
        int r = i >> 7;
        int e = i & 127;
        s_xT[e][r] = (s_half[0][r][e] + s_half[1][r][e]) * (1.f / (float)L_);
    }
    __syncthreads();

    // ---- phase 2: per-metapath linear GEMM ----
    {
        const int j  = tid & 127;
        const int rg = tid >> 7;           // rows rg*2 .. rg*2+1

        const int mt = mp_type_idx[m];
        const float* W = W_mp + mt * (E_ * E_);
        const float bv = b_mp[mt * E_ + j];

        float acc0 = bv, acc1 = bv;

#pragma unroll 2
        for (int ee = 0; ee < E_; ee += 8) {
            float w[8];
#pragma unroll
            for (int u = 0; u < 8; u++) w[u] = W[(ee + u) * E_ + j];
#pragma unroll
            for (int u = 0; u < 8; u++) {
                float2 x = *reinterpret_cast<const float2*>(&s_xT[ee + u][rg * 2]);
                acc0 += x.x * w[u];
                acc1 += x.y * w[u];
            }
        }
        g_agg1[((b0 + rg * 2 + 0) * M_ + m) * E_ + j] = acc0;
        g_agg1[((b0 + rg * 2 + 1) * M_ + m) * E_ + j] = acc1;
    }
}

// ---------------------------------------------------------------------------
// Kernel C: QKV GEMM [2048,128] @ [128,384].
// tile = 8 rows x 128 cols; grid (256, 3) = 768 blocks; 256 threads =
// (col, rowgroup of 4); 4 accumulators; 8-deep weight prefetch; unroll 2.
// ---------------------------------------------------------------------------
__global__ void __launch_bounds__(256) k_qkv(const float* __restrict__ bqkv) {
    __shared__ __align__(16) float s_xT[E_][8];
    const int r0  = blockIdx.x * 8;
    const int cb  = blockIdx.y * 128;
    const int tid = threadIdx.x;
    const int j   = tid & 127;
    const int rg  = tid >> 7;          // rows rg*4 .. rg*4+3

    for (int i = tid; i < 8 * E_; i += 256) {
        int row = i >> 7;
        int e   = i & 127;
        s_xT[e][row] = g_agg1[(r0 + row) * E_ + e];
    }
    __syncthreads();

    const float bv = bqkv[cb + j];
    float acc[4] = {bv, bv, bv, bv};

#pragma unroll 2
    for (int ee = 0; ee < E_; ee += 8) {
        float w[8];
#pragma unroll
        for (int u = 0; u < 8; u++) w[u] = g_WqkvT[(ee + u) * QKV_ + cb + j];
#pragma unroll
        for (int u = 0; u < 8; u++) {
            float4 x = *reinterpret_cast<const float4*>(&s_xT[ee + u][rg * 4]);
            acc[0] += x.x * w[u];
            acc[1] += x.y * w[u];
            acc[2] += x.z * w[u];
            acc[3] += x.w * w[u];
        }
    }
#pragma unroll
    for (int i = 0; i < 4; i++)
        g_qkv[(r0 + rg * 4 + i) * QKV_ + cb + j] = acc[i];
}

// ---------------------------------------------------------------------------
// Kernel D: attention core + output projection.  One batch per block;
// 512 threads; grid 256.
// ---------------------------------------------------------------------------
__global__ void __launch_bounds__(512) k_attnoproj(const float* __restrict__ bo,
                                                   float* __restrict__ out) {
    __shared__ __align__(16) float s_q[M_][QP_];    // 12.5 KB
    __shared__ __align__(16) float s_oT[E_][8];     // attn out transposed [e][m], 4 KB

    const int tid = threadIdx.x;
    const int b   = blockIdx.x;

    // stage qkv rows for this batch (contiguous 12 KB)
    {
        const float4* src = reinterpret_cast<const float4*>(&g_qkv[b * M_ * QKV_]);
        for (int i = tid; i < M_ * QKV_ / 4; i += 512) {
            int m = i / (QKV_ / 4);
            int c = i % (QKV_ / 4);
            *reinterpret_cast<float4*>(&s_q[m][c * 4]) = src[i];
        }
    }
    __syncthreads();

    // attention core: one thread per (h, m)
    if (tid < H_ * M_) {
        const int h  = tid >> 3;
        const int mm = tid & 7;
        const int hb = h * HD_;

        float4 q0 = *reinterpret_cast<const float4*>(&s_q[mm][hb + 0]);
        float4 q1 = *reinterpret_cast<const float4*>(&s_q[mm][hb + 4]);
        float4 q2 = *reinterpret_cast<const float4*>(&s_q[mm][hb + 8]);
        float4 q3 = *reinterpret_cast<const float4*>(&s_q[mm][hb + 12]);

        float s[M_];
        float mx = -1e30f;
#pragma unroll
        for (int n = 0; n < M_; n++) {
            const float* kp = &s_q[n][E_ + hb];
            float4 k0 = *reinterpret_cast<const float4*>(kp + 0);
            float4 k1 = *reinterpret_cast<const float4*>(kp + 4);
            float4 k2 = *reinterpret_cast<const float4*>(kp + 8);
            float4 k3 = *reinterpret_cast<const float4*>(kp + 12);
            float d = q0.x*k0.x + q0.y*k0.y + q0.z*k0.z + q0.w*k0.w
                    + q1.x*k1.x + q1.y*k1.y + q1.z*k1.z + q1.w*k1.w
                    + q2.x*k2.x + q2.y*k2.y + q2.z*k2.z + q2.w*k2.w
                    + q3.x*k3.x + q3.y*k3.y + q3.z*k3.z + q3.w*k3.w;
            s[n] = d * 0.25f;
            mx = fmaxf(mx, s[n]);
        }
        float sum = 0.f;
#pragma unroll
        for (int n = 0; n < M_; n++) { s[n] = __expf(s[n] - mx); sum += s[n]; }
        const float inv = 1.f / sum;

        float o[HD_];
#pragma unroll
        for (int t = 0; t < HD_; t++) o[t] = 0.f;
#pragma unroll
        for (int n = 0; n < M_; n++) {
            float p = s[n] * inv;
            const float* vp = &s_q[n][2 * E_ + hb];
#pragma unroll
            for (int t = 0; t < HD_; t++) o[t] += p * vp[t];
        }
#pragma unroll
        for (int t = 0; t < HD_; t++) s_oT[hb + t][mm] = o[t];
    }
    __syncthreads();

    // output projection: 512 threads = 128 cols x 4 rowgroups of 2 m-rows
    {
        const int j  = tid & 127;
        const int rg = tid >> 7;           // 0..3 -> m-rows rg*2, rg*2+1
        const float bv = bo[j];
        float acc0 = bv, acc1 = bv;

#pragma unroll 2
        for (int ee = 0; ee < E_; ee += 8) {
            float w[8];
#pragma unroll
            for (int u = 0; u < 8; u++) w[u] = g_WoT[(ee + u) * E_ + j];
#pragma unroll
            for (int u = 0; u < 8; u++) {
                float2 x = *reinterpret_cast<const float2*>(&s_oT[ee + u][rg * 2]);
                acc0 += x.x * w[u];
                acc1 += x.y * w[u];
            }
        }
        out[(rg * 2 + 0) * (B_ * E_) + b * E_ + j] = acc0;
        out[(rg * 2 + 1) * (B_ * E_) + b * E_ + j] = acc1;
    }
}

// ---------------------------------------------------------------------------
extern "C" void kernel_launch(void* const* d_in, const int* in_sizes, int n_in,
                              void* d_out, int out_size) {
    (void)in_sizes; (void)n_in; (void)out_size;
    const int*   node_idx    = (const int*)d_in[0];  (void)node_idx;
    const int*   mp_type_idx = (const int*)d_in[1];
    const int*   walks       = (const int*)d_in[2];
    const float* node_table  = (const float*)d_in[3];
    const float* fc1_b       = (const float*)d_in[4];
    const float* edge_table  = (const float*)d_in[5];
    const float* W_mp        = (const float*)d_in[6];
    const float* b_mp        = (const float*)d_in[7];
    const float* Wqkv        = (const float*)d_in[8];
    const float* bqkv        = (const float*)d_in[9];
    const float* Wo          = (const float*)d_in[10];
    const float* bo          = (const float*)d_in[11];
    float* out = (float*)d_out;

    dim3 gAB(M_, B_ / 4);
    k_gathermp<<<gAB, 256>>>(walks, node_table, fc1_b, edge_table,
                             mp_type_idx, W_mp, b_mp, Wqkv, Wo);
    dim3 gQ(R_ / 8, 3);
    k_qkv<<<gQ, 256>>>(bqkv);
    k_attnoproj<<<B_, 512>>>(bo, out);
}

// round 12
// speedup vs baseline: 1.0874x; 1.0874x over previous
#include <cuda_runtime.h>

#define B_   256
#define M_   8
#define L_   64
#define E_   128
#define H_   8
#define HD_  16
#define QKV_ 384
#define QP_  392          // padded qkv row stride in smem
#define R_   (B_ * M_)    // 2048 rows

// Scratch (no allocation allowed -> __device__ globals)
__device__ float g_agg0[R_ * E_];        // mean-fused walk aggregate, row = b*8+m
__device__ float g_agg1[R_ * E_];        // after per-metapath linear, row = b*8+m
__device__ float g_qkv[R_ * QKV_];       // qkv rows
__device__ float g_WqkvT[E_ * QKV_];     // Wqkv transposed: [e][j]
__device__ float g_WoT[E_ * E_];         // Wo transposed:   [e][j]

// ---------------------------------------------------------------------------
// Kernel A: gather + elementwise fuse + mean over walk steps.
// block = (b*M + m); 512 threads = (e in [0,128)) x (walk quarter q in [0,4)).
// Partial sums combined in smem.  Folds the weight transposes (32/block).
// ---------------------------------------------------------------------------
__global__ void __launch_bounds__(512) k_gather(const int*   __restrict__ walks,
                                                const float* __restrict__ node_table,
                                                const float* __restrict__ fc1_b,
                                                const float* __restrict__ edge_table,
                                                const float* __restrict__ Wqkv,
                                                const float* __restrict__ Wo) {
    __shared__ int   s_idx[L_ * 3];
    __shared__ float s_part[4][E_];
    const int bid = blockIdx.x;
    const int tid = threadIdx.x;
    const int e   = tid & 127;
    const int q   = tid >> 7;          // walk quarter 0..3

    // folded transpose: 32 elements per block (2048 blocks x 32 = 65536)
    if (tid < 32) {
        int idx = bid * 32 + tid;
        if (idx < E_ * QKV_) {
            int j = idx / E_;
            int ee = idx % E_;
            g_WqkvT[ee * QKV_ + j] = Wqkv[idx];
        } else {
            int k2 = idx - E_ * QKV_;
            int j = k2 / E_;
            int ee = k2 % E_;
            g_WoT[ee * E_ + j] = Wo[k2];
        }
    }

    const int base = bid * (L_ * 3);
    for (int i = tid; i < L_ * 3; i += 512) s_idx[i] = walks[base + i];
    __syncthreads();

    const float fb = fc1_b[e];
    float acc = 0.f;
    const int l0 = q * (L_ / 4);
#pragma unroll 8
    for (int l = l0; l < l0 + L_ / 4; l++) {
        int n1 = s_idx[3 * l + 0];
        int n2 = s_idx[3 * l + 1];
        int et = s_idx[3 * l + 2];
        float a = node_table[n1 * E_ + e] + fb;
        float b = node_table[n2 * E_ + e] + fb;
        float c = edge_table[et * E_ + e];
        acc += a * b * c;
    }
    s_part[q][e] = acc;
    __syncthreads();

    if (tid < E_) {
        float s = (s_part[0][tid] + s_part[1][tid])
                + (s_part[2][tid] + s_part[3][tid]);
        g_agg0[bid * E_ + tid] = s * (1.f / (float)L_);
    }
}

// ---------------------------------------------------------------------------
// Kernel B: per-metapath linear.  block = (m, 4-batch tile); 256 threads.
// grid = 8 x 64 = 512 blocks.  thread = (col, rowgroup of 2), 2 accumulators.
// 8-deep weight prefetch; unroll 2 -> MLP 16.
// ---------------------------------------------------------------------------
__global__ void __launch_bounds__(256) k_mplinear(const int*   __restrict__ mp_type_idx,
                                                  const float* __restrict__ W_mp,
                                                  const float* __restrict__ b_mp) {
    __shared__ __align__(16) float s_xT[E_][4];
    const int m   = blockIdx.x;
    const int b0  = blockIdx.y * 4;
    const int tid = threadIdx.x;
    const int j   = tid & 127;
    const int rg  = tid >> 7;          // rows rg*2 .. rg*2+1

    for (int i = tid; i < 4 * E_; i += 256) {
        int row = i >> 7;
        int e   = i & 127;
        s_xT[e][row] = g_agg0[((b0 + row) * M_ + m) * E_ + e];
    }
    __syncthreads();

    const int mt = mp_type_idx[m];
    const float* W = W_mp + mt * (E_ * E_);
    const float bv = b_mp[mt * E_ + j];

    float acc0 = bv, acc1 = bv;

#pragma unroll 2
    for (int ee = 0; ee < E_; ee += 8) {
        float w[8];
#pragma unroll
        for (int u = 0; u < 8; u++) w[u] = W[(ee + u) * E_ + j];
#pragma unroll
        for (int u = 0; u < 8; u++) {
            float2 x = *reinterpret_cast<const float2*>(&s_xT[ee + u][rg * 2]);
            acc0 += x.x * w[u];
            acc1 += x.y * w[u];
        }
    }
    g_agg1[((b0 + rg * 2 + 0) * M_ + m) * E_ + j] = acc0;
    g_agg1[((b0 + rg * 2 + 1) * M_ + m) * E_ + j] = acc1;
}

// ---------------------------------------------------------------------------
// Kernel C: QKV GEMM [2048,128] @ [128,384].
// tile = 8 rows x 128 cols; grid (256, 3) = 768 blocks; 256 threads =
// (col, rowgroup of 4); 4 accumulators; 8-deep weight prefetch; unroll 2.
// ---------------------------------------------------------------------------
__global__ void __launch_bounds__(256) k_qkv(const float* __restrict__ bqkv) {
    __shared__ __align__(16) float s_xT[E_][8];
    const int r0  = blockIdx.x * 8;
    const int cb  = blockIdx.y * 128;
    const int tid = threadIdx.x;
    const int j   = tid & 127;
    const int rg  = tid >> 7;          // rows rg*4 .. rg*4+3

    for (int i = tid; i < 8 * E_; i += 256) {
        int row = i >> 7;
        int e   = i & 127;
        s_xT[e][row] = g_agg1[(r0 + row) * E_ + e];
    }
    __syncthreads();

    const float bv = bqkv[cb + j];
    float acc[4] = {bv, bv, bv, bv};

#pragma unroll 2
    for (int ee = 0; ee < E_; ee += 8) {
        float w[8];
#pragma unroll
        for (int u = 0; u < 8; u++) w[u] = g_WqkvT[(ee + u) * QKV_ + cb + j];
#pragma unroll
        for (int u = 0; u < 8; u++) {
            float4 x = *reinterpret_cast<const float4*>(&s_xT[ee + u][rg * 4]);
            acc[0] += x.x * w[u];
            acc[1] += x.y * w[u];
            acc[2] += x.z * w[u];
            acc[3] += x.w * w[u];
        }
    }
#pragma unroll
    for (int i = 0; i < 4; i++)
        g_qkv[(r0 + rg * 4 + i) * QKV_ + cb + j] = acc[i];
}

// ---------------------------------------------------------------------------
// Kernel D: attention core + output projection.  One batch per block;
// 512 threads; grid 256.
// ---------------------------------------------------------------------------
__global__ void __launch_bounds__(512) k_attnoproj(const float* __restrict__ bo,
                                                   float* __restrict__ out) {
    __shared__ __align__(16) float s_q[M_][QP_];    // 12.5 KB
    __shared__ __align__(16) float s_oT[E_][8];     // attn out transposed [e][m], 4 KB

    const int tid = threadIdx.x;
    const int b   = blockIdx.x;

    // stage qkv rows for this batch (contiguous 12 KB)
    {
        const float4* src = reinterpret_cast<const float4*>(&g_qkv[b * M_ * QKV_]);
        for (int i = tid; i < M_ * QKV_ / 4; i += 512) {
            int m = i / (QKV_ / 4);
            int c = i % (QKV_ / 4);
            *reinterpret_cast<float4*>(&s_q[m][c * 4]) = src[i];
        }
    }
    __syncthreads();

    // attention core: one thread per (h, m)
    if (tid < H_ * M_) {
        const int h  = tid >> 3;
        const int mm = tid & 7;
        const int hb = h * HD_;

        float4 q0 = *reinterpret_cast<const float4*>(&s_q[mm][hb + 0]);
        float4 q1 = *reinterpret_cast<const float4*>(&s_q[mm][hb + 4]);
        float4 q2 = *reinterpret_cast<const float4*>(&s_q[mm][hb + 8]);
        float4 q3 = *reinterpret_cast<const float4*>(&s_q[mm][hb + 12]);

        float s[M_];
        float mx = -1e30f;
#pragma unroll
        for (int n = 0; n < M_; n++) {
            const float* kp = &s_q[n][E_ + hb];
            float4 k0 = *reinterpret_cast<const float4*>(kp + 0);
            float4 k1 = *reinterpret_cast<const float4*>(kp + 4);
            float4 k2 = *reinterpret_cast<const float4*>(kp + 8);
            float4 k3 = *reinterpret_cast<const float4*>(kp + 12);
            float d = q0.x*k0.x + q0.y*k0.y + q0.z*k0.z + q0.w*k0.w
                    + q1.x*k1.x + q1.y*k1.y + q1.z*k1.z + q1.w*k1.w
                    + q2.x*k2.x + q2.y*k2.y + q2.z*k2.z + q2.w*k2.w
                    + q3.x*k3.x + q3.y*k3.y + q3.z*k3.z + q3.w*k3.w;
            s[n] = d * 0.25f;
            mx = fmaxf(mx, s[n]);
        }
        float sum = 0.f;
#pragma unroll
        for (int n = 0; n < M_; n++) { s[n] = __expf(s[n] - mx); sum += s[n]; }
        const float inv = 1.f / sum;

        float o[HD_];
#pragma unroll
        for (int t = 0; t < HD_; t++) o[t] = 0.f;
#pragma unroll
        for (int n = 0; n < M_; n++) {
            float p = s[n] * inv;
            const float* vp = &s_q[n][2 * E_ + hb];
#pragma unroll
            for (int t = 0; t < HD_; t++) o[t] += p * vp[t];
        }
#pragma unroll
        for (int t = 0; t < HD_; t++) s_oT[hb + t][mm] = o[t];
    }
    __syncthreads();

    // output projection: 512 threads = 128 cols x 4 rowgroups of 2 m-rows
    {
        const int j  = tid & 127;
        const int rg = tid >> 7;           // 0..3 -> m-rows rg*2, rg*2+1
        const float bv = bo[j];
        float acc0 = bv, acc1 = bv;

#pragma unroll 2
        for (int ee = 0; ee < E_; ee += 8) {
            float w[8];
#pragma unroll
            for (int u = 0; u < 8; u++) w[u] = g_WoT[(ee + u) * E_ + j];
#pragma unroll
            for (int u = 0; u < 8; u++) {
                float2 x = *reinterpret_cast<const float2*>(&s_oT[ee + u][rg * 2]);
                acc0 += x.x * w[u];
                acc1 += x.y * w[u];
            }
        }
        out[(rg * 2 + 0) * (B_ * E_) + b * E_ + j] = acc0;
        out[(rg * 2 + 1) * (B_ * E_) + b * E_ + j] = acc1;
    }
}

// ---------------------------------------------------------------------------
extern "C" void kernel_launch(void* const* d_in, const int* in_sizes, int n_in,
                              void* d_out, int out_size) {
    (void)in_sizes; (void)n_in; (void)out_size;
    const int*   node_idx    = (const int*)d_in[0];  (void)node_idx;
    const int*   mp_type_idx = (const int*)d_in[1];
    const int*   walks       = (const int*)d_in[2];
    const float* node_table  = (const float*)d_in[3];
    const float* fc1_b       = (const float*)d_in[4];
    const float* edge_table  = (const float*)d_in[5];
    const float* W_mp        = (const float*)d_in[6];
    const float* b_mp        = (const float*)d_in[7];
    const float* Wqkv        = (const float*)d_in[8];
    const float* bqkv        = (const float*)d_in[9];
    const float* Wo          = (const float*)d_in[10];
    const float* bo          = (const float*)d_in[11];
    float* out = (float*)d_out;

    k_gather<<<B_ * M_, 512>>>(walks, node_table, fc1_b, edge_table, Wqkv, Wo);
    dim3 gB(M_, B_ / 4);
    k_mplinear<<<gB, 256>>>(mp_type_idx, W_mp, b_mp);
    dim3 gQ(R_ / 8, 3);
    k_qkv<<<gQ, 256>>>(bqkv);
    k_attnoproj<<<B_, 512>>>(bo, out);
}